// round 14
// baseline (speedup 1.0000x reference)
#include <cuda_runtime.h>

// ---------------------------------------------------------------------------
// ST_Block: 66-step spatio-temporal orthogonal basis recursion + fused MLP/BN.
//
// R13: issue-lean GEMM inner loops. Accumulators are COLUMN-major per thread
// (vcol[cc] = V[n0..n0+3][t0+cc]); the A-operand lives transposed ([k][n]) in
// smem so per k-step the loop is exactly: 1 broadcast LDS.128 (a4) +
// 1 LDS.128 (b4) + 16 FFMA  (was 4 scalar LDS + 1 LDS.128 + 16 FFMA).
// Ls is pre-transposed once into g_LsT (k_trans); temporal basis ring
// buffers are stored transposed in smem. Row<->column conversion elsewhere
// is register renaming (free). Persistent kernel + per-chain arrival
// counters (R9), 4-deep g_part, __ldcg/__stcg for mutable slabs.
// ---------------------------------------------------------------------------

#define BB   4
#define CC   16
#define CH   64              // B*C chains
#define NN   512
#define TT   64
#define SLAB (NN*TT)         // 32768 floats per chain slab
#define CSZ  (CH*SLAB)       // floats per full slab
#define NSLAB 4
#define ACCS  3              // slab index for x_st accumulator
#define RTOT  66
#define NB    256            // persistent grid size (co-residency guaranteed)
#define BPAD 68              // padded row stride (floats) for smem tiles
#define BSTRIDE (64*BPAD)    // floats per 64x64 padded buffer

__device__ __align__(16) float g_slab[NSLAB * CSZ];   // ~33.5 MB scratch
__device__ __align__(16) float g_LsT[NN * NN];        // Ls transposed [k][n]
__device__ float g_part[4][CH][8][6];                 // step-mod-4 dot partials
__device__ float g_theta[BB][RTOT];
__device__ int   g_arrive[CH];                        // per-chain arrival counters

__device__ __forceinline__ float4 ldcg4(const float* p) {
    return __ldcg((const float4*)p);
}
__device__ __forceinline__ void stcg4(float* p, float4 v) {
    __stcg((float4*)p, v);
}
__device__ __forceinline__ float d4(float4 a, float4 b) {
    return a.x * b.x + a.y * b.y + a.z * b.z + a.w * b.w;
}
// rows r0..r3 (r_i = M[n0+i][t0..t0+3])  ->  cols c0..c3 (c_j = M[n0..n0+3][t0+j])
__device__ __forceinline__ void trans4(float4 r0, float4 r1, float4 r2, float4 r3,
                                       float4& c0, float4& c1, float4& c2, float4& c3) {
    c0 = make_float4(r0.x, r1.x, r2.x, r3.x);
    c1 = make_float4(r0.y, r1.y, r2.y, r3.y);
    c2 = make_float4(r0.z, r1.z, r2.z, r3.z);
    c3 = make_float4(r0.w, r1.w, r2.w, r3.w);
}

__device__ __forceinline__ float warp_sum(float v) {
    v += __shfl_down_sync(0xffffffffu, v, 16);
    v += __shfl_down_sync(0xffffffffu, v, 8);
    v += __shfl_down_sync(0xffffffffu, v, 4);
    v += __shfl_down_sync(0xffffffffu, v, 2);
    v += __shfl_down_sync(0xffffffffu, v, 1);
    return v;
}

__device__ __forceinline__ void derive_scalars(int buf, int chain, int rUpd,
                                               float* sc) {
    float p0 = 0, p1 = 0, p2 = 0, p3 = 0, p4 = 0, p5 = 0;
    #pragma unroll
    for (int tl = 0; tl < 8; tl++) {
        const float* q = &g_part[buf][chain][tl][0];
        p0 += __ldcg(q + 0); p1 += __ldcg(q + 1); p2 += __ldcg(q + 2);
        p3 += __ldcg(q + 3); p4 += __ldcg(q + 4); p5 += __ldcg(q + 5);
    }
    float d1 = p0;
    float d2 = p1 - d1 * p3;
    float n2 = p2 - 2.f * d1 * p0 - 2.f * d2 * p1
             + d1 * d1 * p4 + d2 * d2 * p5 + 2.f * d1 * d2 * p3;
    sc[0] = d1;
    sc[1] = d2;
    sc[2] = 1.f / fmaxf(sqrtf(fmaxf(n2, 0.f)), 1e-8f);
    sc[3] = g_theta[chain >> 4][rUpd];
}

__device__ __forceinline__ void wait_chain(int chain, int step) {
    int target = 8 * step;
    while (*(volatile int*)&g_arrive[chain] < target) __nanosleep(32);
    __threadfence();
}

// ---------------------------------------------------------------------------
// theta MLP + arrival-counter reset
// ---------------------------------------------------------------------------
__global__ void k_theta(const float* __restrict__ STE, const float* __restrict__ w1,
                        const float* __restrict__ b1, const float* __restrict__ w2,
                        const float* __restrict__ b2) {
    int idx = threadIdx.x;
    if (idx < CH) g_arrive[idx] = 0;
    if (idx >= BB * RTOT) return;
    int b = idx / RTOT, rr = idx % RTOT;
    int q = rr / 11, p = rr % 11;
    float acc = b2[p];
    #pragma unroll
    for (int s = 0; s < 10; s++) {
        float h1 = b1[q];
        #pragma unroll
        for (int t = 0; t < 5; t++)
            h1 += w1[q * 5 + t] * STE[b * 50 + t * 10 + s];
        acc += w2[p * 10 + s] * h1;
    }
    g_theta[b][rr] = fmaxf(acc, 0.f);
}

// ---------------------------------------------------------------------------
// transpose Ls once: g_LsT[k][n] = Ls[n][k]
// ---------------------------------------------------------------------------
__global__ void __launch_bounds__(256) k_trans(const float* __restrict__ Ls) {
    int rrow = blockIdx.x;
    for (int c = threadIdx.x; c < NN; c += 256)
        g_LsT[c * NN + rrow] = Ls[rrow * NN + c];
}

// ---------------------------------------------------------------------------
// init: m00 = x / max(||x||_F, eps) into slab 0; acc = theta_0 * m00
// ---------------------------------------------------------------------------
__global__ void __launch_bounds__(256) k_init(const float* __restrict__ x) {
    int chain = blockIdx.x;
    const float* xp = x + chain * SLAB;
    float* m = g_slab + 0 * CSZ + chain * SLAB;
    float* a = g_slab + ACCS * CSZ + chain * SLAB;
    int tid = threadIdx.x;

    float s = 0.f;
    #pragma unroll
    for (int i = 0; i < 32; i++) {
        float4 v = *(const float4*)(xp + (i * 256 + tid) * 4);
        s += v.x * v.x + v.y * v.y + v.z * v.z + v.w * v.w;
    }
    __shared__ float red[8];
    __shared__ float sinv;
    float w = warp_sum(s);
    if ((tid & 31) == 0) red[tid >> 5] = w;
    __syncthreads();
    if (tid == 0) {
        float t = 0.f;
        #pragma unroll
        for (int k = 0; k < 8; k++) t += red[k];
        sinv = 1.f / fmaxf(sqrtf(t), 1e-8f);
    }
    __syncthreads();
    float inv = sinv;
    float th = g_theta[chain >> 4][0];
    #pragma unroll
    for (int i = 0; i < 32; i++) {
        int o = (i * 256 + tid) * 4;
        float4 v = *(const float4*)(xp + o);
        float4 mm, aa;
        mm.x = v.x * inv; mm.y = v.y * inv; mm.z = v.z * inv; mm.w = v.w * inv;
        aa.x = th * mm.x; aa.y = th * mm.y; aa.z = th * mm.z; aa.w = th * mm.w;
        *(float4*)(m + o) = mm;
        *(float4*)(a + o) = aa;
    }
}

// ---------------------------------------------------------------------------
// persistent kernel. Thread (tx = tid&15, tyv = tid>>4): t0 = 4*tx, n0 = 4*tyv.
// vcol[slot][cc] = raw V[n0..n0+3][t0+cc] (column-major accumulators).
// dyn smem: 4 transposed basis buffers BT (2 slots x 2 parities, [t][n]),
// then bufA (Ls chunk transposed [k][n] / Lt rows [k][u]) and bufB (X rows).
// ---------------------------------------------------------------------------
__global__ void __launch_bounds__(256, 2) k_persist(
    const float* __restrict__ Lt)
{
    extern __shared__ float dyn[];
    float* Bb = dyn;                                   // 4 transposed buffers
    float* bufA = dyn + 4 * BSTRIDE;                   // [64][BPAD]
    float* bufB = dyn + 5 * BSTRIDE;                   // [64][BPAD]
    __shared__ float scal[4];
    __shared__ float red[8][6];
    const int tid = threadIdx.x, bid = blockIdx.x;
    const int tx = tid & 15, tyv = tid >> 4;
    const int t0 = tx << 2, n0 = tyv << 2;

    int chainA[2], baseA[2], rtA[2];
    #pragma unroll
    for (int slot = 0; slot < 2; slot++) {
        int tt = bid + slot * NB;
        chainA[slot] = tt >> 3;
        rtA[slot] = tt & 7;
        baseA[slot] = (tt >> 3) * SLAB + (tt & 7) * 64 * TT;
    }
    float4 vcol[2][4];

    int r = 1;
    for (int i = 0; i <= 10; i++) {
        if (i > 0) {
            // ================= SPATIAL PHASE (step r) =================
            int inS = (i - 1) % 3;
            int secS = (i >= 2) ? (i + 1) % 3 : -1;    // == (i-2)%3
            #pragma unroll 1
            for (int slot = 0; slot < 2; slot++) {
                int chain = chainA[slot], base = baseA[slot], rt = rtA[slot];
                const float* BT0 = Bb + (slot * 2 + 0) * BSTRIDE;   // m_{.,5}
                const float* BT1 = Bb + (slot * 2 + 1) * BSTRIDE;   // m_{.,4}
                // prologue: normalize pending temporal V (step r-1) -> acc
                if (tid == 0) {
                    wait_chain(chain, r - 1);
                    derive_scalars((r - 1) & 3, chain, r - 1, scal);
                }
                __syncthreads();
                {
                    float dd1 = scal[0], dd2 = scal[1], inv = scal[2], th = scal[3];
                    float4 mc[4];
                    #pragma unroll
                    for (int cc = 0; cc < 4; cc++) {
                        float4 l = *(const float4*)&BT0[(t0 + cc) * BPAD + n0];
                        float4 s4 = *(const float4*)&BT1[(t0 + cc) * BPAD + n0];
                        float4 v = vcol[slot][cc];
                        mc[cc].x = (v.x - dd1 * l.x - dd2 * s4.x) * inv;
                        mc[cc].y = (v.y - dd1 * l.y - dd2 * s4.y) * inv;
                        mc[cc].z = (v.z - dd1 * l.z - dd2 * s4.z) * inv;
                        mc[cc].w = (v.w - dd1 * l.w - dd2 * s4.w) * inv;
                    }
                    float4 m0, m1, m2, m3;
                    trans4(mc[0], mc[1], mc[2], mc[3], m0, m1, m2, m3);
                    // rows of m are (m0..m3)? trans of cols gives rows:
                    // row_i = {mc[0][i], mc[1][i], mc[2][i], mc[3][i]}
                    float* A = g_slab + ACCS * CSZ + base;
                    float4 mr[4] = {m0, m1, m2, m3};
                    #pragma unroll
                    for (int ii = 0; ii < 4; ii++) {
                        float* ap = A + (n0 + ii) * TT + t0;
                        float4 a = *(float4*)ap;
                        a.x += th * mr[ii].x; a.y += th * mr[ii].y;
                        a.z += th * mr[ii].z; a.w += th * mr[ii].w;
                        *(float4*)ap = a;
                    }
                }
                // spatial GEMM: V[n][t] = sum_k Ls[n][k] X[k][t]
                const float* Xc = g_slab + inS * CSZ + chain * SLAB;
                #pragma unroll
                for (int cc = 0; cc < 4; cc++)
                    vcol[slot][cc] = make_float4(0.f, 0.f, 0.f, 0.f);
                for (int kc = 0; kc < 8; kc++) {
                    __syncthreads();
                    #pragma unroll
                    for (int it = 0; it < 4; it++) {
                        int li = it * 256 + tid;
                        int rr = li >> 4, c4 = (li & 15) << 2;
                        *(float4*)&bufA[rr * BPAD + c4] =
                            *(const float4*)(g_LsT + (kc * 64 + rr) * NN + rt * 64 + c4);
                        *(float4*)&bufB[rr * BPAD + c4] =
                            ldcg4(Xc + (kc * 64 + rr) * TT + c4);
                    }
                    __syncthreads();
                    #pragma unroll 8
                    for (int k = 0; k < 64; k++) {
                        float4 a4 = *(float4*)&bufA[k * BPAD + n0];
                        float4 b4 = *(float4*)&bufB[k * BPAD + t0];
                        vcol[slot][0].x += a4.x * b4.x; vcol[slot][0].y += a4.y * b4.x;
                        vcol[slot][0].z += a4.z * b4.x; vcol[slot][0].w += a4.w * b4.x;
                        vcol[slot][1].x += a4.x * b4.y; vcol[slot][1].y += a4.y * b4.y;
                        vcol[slot][1].z += a4.z * b4.y; vcol[slot][1].w += a4.w * b4.y;
                        vcol[slot][2].x += a4.x * b4.z; vcol[slot][2].y += a4.y * b4.z;
                        vcol[slot][2].z += a4.z * b4.z; vcol[slot][2].w += a4.w * b4.z;
                        vcol[slot][3].x += a4.x * b4.w; vcol[slot][3].y += a4.y * b4.w;
                        vcol[slot][3].z += a4.z * b4.w; vcol[slot][3].w += a4.w * b4.w;
                    }
                }
                // dots: L = slab[inS] tile rows, S = slab[secS] or 0
                const float* Lr = g_slab + inS * CSZ + base;
                const float* S2 = (secS >= 0) ? (g_slab + secS * CSZ + base) : nullptr;
                float4 lc[4], sc4[4];
                {
                    float4 l0 = ldcg4(Lr + (n0 + 0) * TT + t0);
                    float4 l1 = ldcg4(Lr + (n0 + 1) * TT + t0);
                    float4 l2 = ldcg4(Lr + (n0 + 2) * TT + t0);
                    float4 l3 = ldcg4(Lr + (n0 + 3) * TT + t0);
                    trans4(l0, l1, l2, l3, lc[0], lc[1], lc[2], lc[3]);
                    if (S2) {
                        float4 s0r = ldcg4(S2 + (n0 + 0) * TT + t0);
                        float4 s1r = ldcg4(S2 + (n0 + 1) * TT + t0);
                        float4 s2r = ldcg4(S2 + (n0 + 2) * TT + t0);
                        float4 s3r = ldcg4(S2 + (n0 + 3) * TT + t0);
                        trans4(s0r, s1r, s2r, s3r, sc4[0], sc4[1], sc4[2], sc4[3]);
                    } else {
                        #pragma unroll
                        for (int cc = 0; cc < 4; cc++)
                            sc4[cc] = make_float4(0.f, 0.f, 0.f, 0.f);
                    }
                }
                float q1 = 0, q2 = 0, q3 = 0, q4 = 0, q5 = 0, q6 = 0;
                #pragma unroll
                for (int cc = 0; cc < 4; cc++) {
                    float4 vv = vcol[slot][cc];
                    q1 += d4(vv, lc[cc]);  q2 += d4(vv, sc4[cc]);
                    q3 += d4(vv, vv);      q4 += d4(lc[cc], sc4[cc]);
                    q5 += d4(lc[cc], lc[cc]); q6 += d4(sc4[cc], sc4[cc]);
                }
                float r6[6] = {q1, q2, q3, q4, q5, q6};
                #pragma unroll
                for (int s = 0; s < 6; s++) {
                    float w = warp_sum(r6[s]);
                    if ((tid & 31) == 0) red[tid >> 5][s] = w;
                }
                __syncthreads();
                if (tid == 0) {
                    #pragma unroll
                    for (int s = 0; s < 6; s++) {
                        float t = 0.f;
                        #pragma unroll
                        for (int w = 0; w < 8; w++) t += red[w][s];
                        __stcg(&g_part[r & 3][chain][rtA[slot]][s], t);
                    }
                    __threadfence();
                    atomicAdd(&g_arrive[chain], 1);
                }
                __syncthreads();
            }
            r++;
        }
        // ================= TEMPORAL PHASES j = 1..5 =================
        for (int j = 1; j <= 5; j++) {
            // Lt rows into bufA (spatial clobbered it)
            #pragma unroll
            for (int it = 0; it < 4; it++) {
                int li = it * 256 + tid;
                int rr = li >> 4, c4 = (li & 15) << 2;
                *(float4*)&bufA[rr * BPAD + c4] = *(const float4*)(Lt + rr * TT + c4);
            }
            int curPar = (j - 1) & 1;
            #pragma unroll 1
            for (int slot = 0; slot < 2; slot++) {
                int chain = chainA[slot], base = baseA[slot];
                float* BTc = Bb + (slot * 2 + curPar) * BSTRIDE;
                float* BTo = Bb + (slot * 2 + (curPar ^ 1)) * BSTRIDE;
                if (i == 0 && j == 1) {
                    // load m00 tile (rows) -> transposed BTc
                    const float* M0 = g_slab + 0 * CSZ + base;
                    float4 r0 = ldcg4(M0 + (n0 + 0) * TT + t0);
                    float4 r1 = ldcg4(M0 + (n0 + 1) * TT + t0);
                    float4 r2 = ldcg4(M0 + (n0 + 2) * TT + t0);
                    float4 r3 = ldcg4(M0 + (n0 + 3) * TT + t0);
                    float4 c0, c1, c2, c3;
                    trans4(r0, r1, r2, r3, c0, c1, c2, c3);
                    *(float4*)&BTc[(t0 + 0) * BPAD + n0] = c0;
                    *(float4*)&BTc[(t0 + 1) * BPAD + n0] = c1;
                    *(float4*)&BTc[(t0 + 2) * BPAD + n0] = c2;
                    *(float4*)&BTc[(t0 + 3) * BPAD + n0] = c3;
                } else {
                    if (tid == 0) {
                        wait_chain(chain, r - 1);
                        derive_scalars((r - 1) & 3, chain, r - 1, scal);
                    }
                    __syncthreads();
                    float dd1 = scal[0], dd2 = scal[1], inv = scal[2], th = scal[3];
                    float4 lc[4], sc4[4], mc[4];
                    if (j == 1) {
                        const float* Lg = g_slab + ((i - 1) % 3) * CSZ + base;
                        float4 l0 = ldcg4(Lg + (n0 + 0) * TT + t0);
                        float4 l1 = ldcg4(Lg + (n0 + 1) * TT + t0);
                        float4 l2 = ldcg4(Lg + (n0 + 2) * TT + t0);
                        float4 l3 = ldcg4(Lg + (n0 + 3) * TT + t0);
                        trans4(l0, l1, l2, l3, lc[0], lc[1], lc[2], lc[3]);
                        if (i >= 2) {
                            const float* Sg = g_slab + ((i + 1) % 3) * CSZ + base;
                            float4 s0r = ldcg4(Sg + (n0 + 0) * TT + t0);
                            float4 s1r = ldcg4(Sg + (n0 + 1) * TT + t0);
                            float4 s2r = ldcg4(Sg + (n0 + 2) * TT + t0);
                            float4 s3r = ldcg4(Sg + (n0 + 3) * TT + t0);
                            trans4(s0r, s1r, s2r, s3r, sc4[0], sc4[1], sc4[2], sc4[3]);
                        } else {
                            #pragma unroll
                            for (int cc = 0; cc < 4; cc++)
                                sc4[cc] = make_float4(0.f, 0.f, 0.f, 0.f);
                        }
                    } else {
                        #pragma unroll
                        for (int cc = 0; cc < 4; cc++) {
                            lc[cc] = *(const float4*)&BTo[(t0 + cc) * BPAD + n0];
                            sc4[cc] = (j == 2) ? make_float4(0.f, 0.f, 0.f, 0.f)
                                    : *(const float4*)&BTc[(t0 + cc) * BPAD + n0];
                        }
                    }
                    #pragma unroll
                    for (int cc = 0; cc < 4; cc++) {
                        float4 v = vcol[slot][cc];
                        mc[cc].x = (v.x - dd1 * lc[cc].x - dd2 * sc4[cc].x) * inv;
                        mc[cc].y = (v.y - dd1 * lc[cc].y - dd2 * sc4[cc].y) * inv;
                        mc[cc].z = (v.z - dd1 * lc[cc].z - dd2 * sc4[cc].z) * inv;
                        mc[cc].w = (v.w - dd1 * lc[cc].w - dd2 * sc4[cc].w) * inv;
                        *(float4*)&BTc[(t0 + cc) * BPAD + n0] = mc[cc];
                    }
                    float4 mr0, mr1, mr2, mr3;
                    trans4(mc[0], mc[1], mc[2], mc[3], mr0, mr1, mr2, mr3);
                    float4 mr[4] = {mr0, mr1, mr2, mr3};
                    if (j == 1) {                       // persist spatial m
                        float* Mg = g_slab + (i % 3) * CSZ + base;
                        #pragma unroll
                        for (int ii = 0; ii < 4; ii++)
                            stcg4(Mg + (n0 + ii) * TT + t0, mr[ii]);
                    }
                    float* A = g_slab + ACCS * CSZ + base;
                    #pragma unroll
                    for (int ii = 0; ii < 4; ii++) {
                        float* ap = A + (n0 + ii) * TT + t0;
                        float4 a = *(float4*)ap;
                        a.x += th * mr[ii].x; a.y += th * mr[ii].y;
                        a.z += th * mr[ii].z; a.w += th * mr[ii].w;
                        *(float4*)ap = a;
                    }
                }
                __syncthreads();            // BTc + bufA visible
                // temporal GEMM: V[n][u] = sum_k m[n][k] * Lt[k][u]
                #pragma unroll
                for (int cc = 0; cc < 4; cc++)
                    vcol[slot][cc] = make_float4(0.f, 0.f, 0.f, 0.f);
                #pragma unroll 8
                for (int k = 0; k < 64; k++) {
                    float4 a4 = *(float4*)&BTc[k * BPAD + n0];
                    float4 b4 = *(float4*)&bufA[k * BPAD + t0];
                    vcol[slot][0].x += a4.x * b4.x; vcol[slot][0].y += a4.y * b4.x;
                    vcol[slot][0].z += a4.z * b4.x; vcol[slot][0].w += a4.w * b4.x;
                    vcol[slot][1].x += a4.x * b4.y; vcol[slot][1].y += a4.y * b4.y;
                    vcol[slot][1].z += a4.z * b4.y; vcol[slot][1].w += a4.w * b4.y;
                    vcol[slot][2].x += a4.x * b4.z; vcol[slot][2].y += a4.y * b4.z;
                    vcol[slot][2].z += a4.z * b4.z; vcol[slot][2].w += a4.w * b4.z;
                    vcol[slot][3].x += a4.x * b4.w; vcol[slot][3].y += a4.y * b4.w;
                    vcol[slot][3].z += a4.z * b4.w; vcol[slot][3].w += a4.w * b4.w;
                }
                // dots: L = m_{j-1} (BTc), S = m_{j-2} (BTo) or 0
                float q1 = 0, q2 = 0, q3 = 0, q4 = 0, q5 = 0, q6 = 0;
                #pragma unroll
                for (int cc = 0; cc < 4; cc++) {
                    float4 lv = *(const float4*)&BTc[(t0 + cc) * BPAD + n0];
                    float4 sv = (j == 1) ? make_float4(0.f, 0.f, 0.f, 0.f)
                               : *(const float4*)&BTo[(t0 + cc) * BPAD + n0];
                    float4 vv = vcol[slot][cc];
                    q1 += d4(vv, lv);  q2 += d4(vv, sv);
                    q3 += d4(vv, vv);  q4 += d4(lv, sv);
                    q5 += d4(lv, lv);  q6 += d4(sv, sv);
                }
                float r6[6] = {q1, q2, q3, q4, q5, q6};
                #pragma unroll
                for (int s = 0; s < 6; s++) {
                    float w = warp_sum(r6[s]);
                    if ((tid & 31) == 0) red[tid >> 5][s] = w;
                }
                __syncthreads();
                if (tid == 0) {
                    #pragma unroll
                    for (int s = 0; s < 6; s++) {
                        float t = 0.f;
                        #pragma unroll
                        for (int w = 0; w < 8; w++) t += red[w][s];
                        __stcg(&g_part[r & 3][chain][rtA[slot]][s], t);
                    }
                    __threadfence();
                    atomicAdd(&g_arrive[chain], 1);
                }
                __syncthreads();
            }
            r++;
        }
    }
    // ---------------- final pending normalize (step 65): A += theta*m -------
    #pragma unroll 1
    for (int slot = 0; slot < 2; slot++) {
        int chain = chainA[slot], base = baseA[slot];
        const float* BT0 = Bb + (slot * 2 + 0) * BSTRIDE;   // m5
        const float* BT1 = Bb + (slot * 2 + 1) * BSTRIDE;   // m4
        if (tid == 0) {
            wait_chain(chain, r - 1);
            derive_scalars((r - 1) & 3, chain, r - 1, scal);
        }
        __syncthreads();
        float dd1 = scal[0], dd2 = scal[1], inv = scal[2], th = scal[3];
        float4 mc[4];
        #pragma unroll
        for (int cc = 0; cc < 4; cc++) {
            float4 l = *(const float4*)&BT0[(t0 + cc) * BPAD + n0];
            float4 s4 = *(const float4*)&BT1[(t0 + cc) * BPAD + n0];
            float4 v = vcol[slot][cc];
            mc[cc].x = (v.x - dd1 * l.x - dd2 * s4.x) * inv;
            mc[cc].y = (v.y - dd1 * l.y - dd2 * s4.y) * inv;
            mc[cc].z = (v.z - dd1 * l.z - dd2 * s4.z) * inv;
            mc[cc].w = (v.w - dd1 * l.w - dd2 * s4.w) * inv;
        }
        float4 mr0, mr1, mr2, mr3;
        trans4(mc[0], mc[1], mc[2], mc[3], mr0, mr1, mr2, mr3);
        float4 mr[4] = {mr0, mr1, mr2, mr3};
        float* A = g_slab + ACCS * CSZ + base;
        #pragma unroll
        for (int ii = 0; ii < 4; ii++) {
            float* ap = A + (n0 + ii) * TT + t0;
            float4 a = *(float4*)ap;
            a.x += th * mr[ii].x; a.y += th * mr[ii].y;
            a.z += th * mr[ii].z; a.w += th * mr[ii].w;
            *(float4*)ap = a;
        }
        __syncthreads();
    }
}

// ---------------------------------------------------------------------------
// final: out[b,o,n,t] = BN(W_mlp @ cat(x, x_st) + b)  (BN folded)
// ---------------------------------------------------------------------------
__global__ void __launch_bounds__(256) k_final(const float* __restrict__ x,
                                               const float* __restrict__ wm,
                                               const float* __restrict__ bm,
                                               const float* __restrict__ gam,
                                               const float* __restrict__ bet,
                                               const float* __restrict__ mea,
                                               const float* __restrict__ var,
                                               float* __restrict__ out) {
    int b = blockIdx.x;
    int ng = blockIdx.y;                 // group of 4 n values
    __shared__ float sV[4][32][65];
    __shared__ float sW[64][32];
    __shared__ float sb2[64];
    int tid = threadIdx.x;

    for (int i = tid; i < 2048; i += 256) {
        int o = i >> 5, c = i & 31;
        float inv = gam[o] * rsqrtf(var[o] + 1e-5f);
        sW[o][c] = wm[o * 32 + c] * inv;
    }
    if (tid < 64) {
        float inv = gam[tid] * rsqrtf(var[tid] + 1e-5f);
        sb2[tid] = bm[tid] * inv + bet[tid] - mea[tid] * inv;
    }
    for (int i = tid; i < 8192; i += 256) {
        int t = i & 63, c = (i >> 6) & 31, nn = i >> 11;
        int n = ng * 4 + nn;
        float val;
        if (c < 16) val = x[((b * CC + c) * NN + n) * TT + t];
        else        val = g_slab[ACCS * CSZ + (b * CC + (c - 16)) * SLAB + n * TT + t];
        sV[nn][c][t] = val;
    }
    __syncthreads();

    int tg = tid & 63, og = tid >> 6;
    #pragma unroll 1
    for (int oo = 0; oo < 16; oo++) {
        int o = og * 16 + oo;
        float bb = sb2[o];
        float a0 = bb, a1 = bb, a2 = bb, a3 = bb;
        #pragma unroll
        for (int c = 0; c < 32; c++) {
            float w = sW[o][c];
            a0 += w * sV[0][c][tg];
            a1 += w * sV[1][c][tg];
            a2 += w * sV[2][c][tg];
            a3 += w * sV[3][c][tg];
        }
        int n0 = ng * 4;
        float* op = out + ((b * 64 + o) * NN + n0) * TT + tg;
        op[0 * TT] = a0;
        op[1 * TT] = a1;
        op[2 * TT] = a2;
        op[3 * TT] = a3;
    }
}

// ---------------------------------------------------------------------------
// host: 5-node launch sequence (graph-capturable: launches only)
// ---------------------------------------------------------------------------
extern "C" void kernel_launch(void* const* d_in, const int* in_sizes, int n_in,
                              void* d_out, int out_size) {
    const float* x   = (const float*)d_in[0];
    const float* Ls  = (const float*)d_in[1];
    const float* Lt  = (const float*)d_in[2];
    const float* STE = (const float*)d_in[3];
    const float* w1  = (const float*)d_in[4];
    const float* b1  = (const float*)d_in[5];
    const float* w2  = (const float*)d_in[6];
    const float* b2  = (const float*)d_in[7];
    const float* wm  = (const float*)d_in[8];
    const float* bm  = (const float*)d_in[9];
    const float* gam = (const float*)d_in[10];
    const float* bet = (const float*)d_in[11];
    const float* mea = (const float*)d_in[12];
    const float* var = (const float*)d_in[13];
    float* out = (float*)d_out;
    (void)in_sizes; (void)n_in; (void)out_size;

    const int dynBytes = 6 * BSTRIDE * (int)sizeof(float);   // 104448
    cudaFuncSetAttribute(k_persist,
                         cudaFuncAttributeMaxDynamicSharedMemorySize, dynBytes);

    k_theta<<<1, 288>>>(STE, w1, b1, w2, b2);
    k_trans<<<NN, 256>>>(Ls);
    k_init<<<64, 256>>>(x);
    k_persist<<<NB, 256, dynBytes>>>(Lt);
    k_final<<<dim3(4, 128), 256>>>(x, wm, bm, gam, bet, mea, var, out);
}